// round 2
// baseline (speedup 1.0000x reference)
#include <cuda_runtime.h>
#include <cuda_bf16.h>

#define S_GRID 14
#define INV_S (1.0f / 14.0f)
#define L_COORD 5.0f
#define L_NOOBJ 0.5f

// Accumulators: [0]=reg, [1]=contain, [2]=noobj, [3]=cls
__device__ float g_acc[4];

__global__ void yolo_init_kernel() {
    if (threadIdx.x < 4) g_acc[threadIdx.x] = 0.0f;
}

__device__ __forceinline__ float iou_vs_tgt(float x, float y, float w, float h,
                                            float tx1, float ty1, float tx2, float ty2,
                                            float ta) {
    float cx = x * INV_S;
    float cy = y * INV_S;
    float x1 = cx - 0.5f * w, y1 = cy - 0.5f * h;
    float x2 = cx + 0.5f * w, y2 = cy + 0.5f * h;
    float lx = fmaxf(x1, tx1), ly = fmaxf(y1, ty1);
    float rx = fminf(x2, tx2), ry = fminf(y2, ty2);
    float iw = fmaxf(rx - lx, 0.0f), ih = fmaxf(ry - ly, 0.0f);
    float inter = iw * ih;
    float a1 = (x2 - x1) * (y2 - y1);
    return inter / (a1 + ta - inter);
}

__global__ void __launch_bounds__(256) yolo_main_kernel(
    const float* __restrict__ pred,            // [ncells, 30]
    const float* __restrict__ tbox,            // [ncells, 4]
    const float* __restrict__ tcls,            // [ncells, 20]
    const unsigned int* __restrict__ objmap,   // [ncells] bool widened to 4-byte (int32 or f32)
    int ncells) {

    int i = blockIdx.x * blockDim.x + threadIdx.x;

    float reg = 0.0f, contain = 0.0f, noobj = 0.0f, cls = 0.0f;

    if (i < ncells) {
        const float* p = pred + (size_t)i * 30;
        // Works for int32 (1 -> nonzero) and float32 (1.0f -> 0x3F800000 nonzero).
        bool has_obj = objmap[i] != 0u;

        if (!has_obj) {
            // Only the two confidences matter for no-object cells.
            float c1 = __ldg(p + 4);
            float c2 = __ldg(p + 9);
            noobj = L_NOOBJ * (c1 * c1 + c2 * c2);
        } else {
            // Full row: 30 floats via 15 aligned float2 (row stride 120B, 8B aligned)
            float pv[30];
            #pragma unroll
            for (int j = 0; j < 15; j++) {
                float2 v = *reinterpret_cast<const float2*>(p + 2 * j);
                pv[2 * j]     = v.x;
                pv[2 * j + 1] = v.y;
            }
            float4 tb = *reinterpret_cast<const float4*>(tbox + (size_t)i * 4);

            // class loss: 20 floats, 5 aligned float4 (row 80B, 16B aligned)
            const float* tc = tcls + (size_t)i * 20;
            float csum = 0.0f;
            #pragma unroll
            for (int j = 0; j < 5; j++) {
                float4 t = *reinterpret_cast<const float4*>(tc + 4 * j);
                float d0 = pv[10 + 4 * j + 0] - t.x;
                float d1 = pv[10 + 4 * j + 1] - t.y;
                float d2 = pv[10 + 4 * j + 2] - t.z;
                float d3 = pv[10 + 4 * j + 3] - t.w;
                csum += d0 * d0 + d1 * d1 + d2 * d2 + d3 * d3;
            }
            cls = csum;

            // target box xyxy + area
            float tcx = tb.x * INV_S, tcy = tb.y * INV_S;
            float tx1 = tcx - 0.5f * tb.z, ty1 = tcy - 0.5f * tb.w;
            float tx2 = tcx + 0.5f * tb.z, ty2 = tcy + 0.5f * tb.w;
            float ta = (tx2 - tx1) * (ty2 - ty1);

            float iou1 = iou_vs_tgt(pv[0], pv[1], pv[2], pv[3], tx1, ty1, tx2, ty2, ta);
            float iou2 = iou_vs_tgt(pv[5], pv[6], pv[7], pv[8], tx1, ty1, tx2, ty2, ta);

            bool take1 = iou1 > iou2;
            float best_iou = take1 ? iou1 : iou2;
            float bx = take1 ? pv[0] : pv[5];
            float by = take1 ? pv[1] : pv[6];
            float bw = take1 ? pv[2] : pv[7];
            float bh = take1 ? pv[3] : pv[8];
            float bc = take1 ? pv[4] : pv[9];

            float dx = bx - tb.x, dy = by - tb.y;
            float xy_err = dx * dx + dy * dy;
            float dw = sqrtf(bw) - sqrtf(tb.z);
            float dh = sqrtf(bh) - sqrtf(tb.w);
            float wh_err = dw * dw + dh * dh;
            reg = L_COORD * (xy_err + wh_err);

            float dc = bc - best_iou;
            contain = dc * dc;
        }
    }

    // Warp reduce (4 values)
    #pragma unroll
    for (int off = 16; off > 0; off >>= 1) {
        reg     += __shfl_down_sync(0xFFFFFFFFu, reg, off);
        contain += __shfl_down_sync(0xFFFFFFFFu, contain, off);
        noobj   += __shfl_down_sync(0xFFFFFFFFu, noobj, off);
        cls     += __shfl_down_sync(0xFFFFFFFFu, cls, off);
    }

    __shared__ float s_red[8][4];
    int lane = threadIdx.x & 31;
    int warp = threadIdx.x >> 5;
    if (lane == 0) {
        s_red[warp][0] = reg;
        s_red[warp][1] = contain;
        s_red[warp][2] = noobj;
        s_red[warp][3] = cls;
    }
    __syncthreads();
    if (warp == 0) {
        // 4 components x 8 warps = 32 lanes
        int comp = lane >> 3;     // 0..3
        int w    = lane & 7;      // 0..7
        float v = s_red[w][comp];
        v += __shfl_down_sync(0xFFFFFFFFu, v, 4);
        v += __shfl_down_sync(0xFFFFFFFFu, v, 2);
        v += __shfl_down_sync(0xFFFFFFFFu, v, 1);
        if (w == 0) atomicAdd(&g_acc[comp], v);
    }
}

__global__ void yolo_finalize_kernel(float* __restrict__ out, float inv_n) {
    float reg     = g_acc[0];
    float contain = g_acc[1];
    float noobj   = g_acc[2];
    float cls     = g_acc[3];
    float total = reg + contain + noobj + cls;
    out[0] = total * inv_n;
    out[1] = reg * inv_n;
    out[2] = contain * inv_n;
    out[3] = noobj * inv_n;
    out[4] = cls * inv_n;
}

extern "C" void kernel_launch(void* const* d_in, const int* in_sizes, int n_in,
                              void* d_out, int out_size) {
    const float* pred = (const float*)d_in[0];
    const float* tbox = (const float*)d_in[1];
    const float* tcls = (const float*)d_in[2];
    const unsigned int* objmap = (const unsigned int*)d_in[3];

    int ncells = in_sizes[1] / 4;             // target_boxes has 4 per cell
    int n_imgs = ncells / (S_GRID * S_GRID);  // 4096

    yolo_init_kernel<<<1, 32>>>();
    int threads = 256;
    int blocks = (ncells + threads - 1) / threads;
    yolo_main_kernel<<<blocks, threads>>>(pred, tbox, tcls, objmap, ncells);
    yolo_finalize_kernel<<<1, 1>>>((float*)d_out, 1.0f / (float)n_imgs);
}